// round 14
// baseline (speedup 1.0000x reference)
#include <cuda_runtime.h>
#include <cuda_bf16.h>
#include <math.h>

// out[j] = sum_{m=0}^{199} eigenvectors[l][m][n] * basis(m, x[j])
//   l==0: cos((pi/10)(m+0.5)x)   l>0: sin((pi/10)(m+1)x)
//
// R11: SINGLE fused kernel. Blocks 0..32 tabulate F over [-pi,pi] (8192
// intervals) as per-interval Catmull-Rom cubic coeffs (float4, 128KB,
// L1-resident); blocks 33.. evaluate: x-load prologue FIRST (hides DRAM
// latency under the build), then acquire-spin on a completion flag, then one
// LDG.128 + 3 fma per point. Last eval block resets the flag so every CUDA
// graph replay starts clean. All 1010 blocks fit in wave 1 -> no deadlock.

#define N_MAX    200
#define M_TERMS  200
#define GRID_G   8192               // intervals over [-pi, pi]
#define BLOCK    256
#define EPB      253                // coeff entries per build block
#define BGRID    33                 // ceil(8192/253)

__device__ float4 g_coef[GRID_G];
__device__ int    g_flag       = 0;   // build-done flag
__device__ int    g_build_done = 0;   // build blocks finished
__device__ int    g_eval_done  = 0;   // eval blocks finished

__device__ __forceinline__ int ld_acquire(int* p) {
    int v;
    asm volatile("ld.acquire.gpu.global.b32 %0, [%1];" : "=r"(v) : "l"(p) : "memory");
    return v;
}
__device__ __forceinline__ void st_release(int* p, int v) {
    asm volatile("st.release.gpu.global.b32 [%0], %1;" :: "l"(p), "r"(v) : "memory");
}

__device__ __forceinline__ float eval_one(float f, int i)
{
    float4 k = __ldg(&g_coef[i]);             // one LDG.128, L1-resident
    float r  = fmaf(f, k.w, k.z);
    r        = fmaf(f, r, k.y);
    return     fmaf(f, r, k.x);
}

__global__ __launch_bounds__(BLOCK)
void fused_kernel(const int* __restrict__ np,
                  const int* __restrict__ lp,
                  const float4* __restrict__ x4,
                  const float* __restrict__ x,
                  const float* __restrict__ eig,
                  float4* __restrict__ out4,
                  float* __restrict__ out,
                  int N4, int N, int egrid)
{
    const int bid = blockIdx.x;

    if (bid < BGRID) {
        // ---------------- build part ----------------
        __shared__ float sc[M_TERMS];
        __shared__ float fv[BLOCK];

        const int n = np[0];
        const int l = lp[0];
        const float* base = eig + (size_t)l * (N_MAX * N_MAX) + n;
        for (int m = threadIdx.x; m < M_TERMS; m += BLOCK)
            sc[m] = base[(size_t)m * N_MAX];
        __syncthreads();

        const int s = bid * EPB - 1;             // first value index
        const int v = s + threadIdx.x;

        const float u = (float)((double)v * (6.283185307179586 / GRID_G)
                                - 3.141592653589793);
        float si, c;
        sincosf(u, &si, &c);
        const float c22 = fmaf(4.0f * c, c, -2.0f);   // 2cos(2u)

        float pe, pem, po, pom;
        if (l == 0) {
            float h0 = cosf(0.5f * u);
            pe  = h0;                    // p_0  = cos(u/2)
            pem = cosf(1.5f * u);        // p_{-2}= cos(-1.5u)
            po  = pem;                   // p_1  = cos(1.5u)
            pom = h0;                    // p_{-1}= cos(u/2)
        } else {
            pe  = si;                    // p_0  = sin(u)
            pem = -si;                   // p_{-2}= sin(-u)
            po  = 2.0f * si * c;         // p_1  = sin(2u)
            pom = 0.0f;                  // p_{-1}= sin(0)
        }

        float acce = 0.0f, acco = 0.0f;
        #pragma unroll 4
        for (int m = 0; m < M_TERMS; m += 2) {
            acce = fmaf(sc[m],     pe, acce);
            acco = fmaf(sc[m + 1], po, acco);
            float pne = fmaf(c22, pe, -pem);
            float pno = fmaf(c22, po, -pom);
            pem = pe; pe = pne;
            pom = po; po = pno;
        }
        fv[threadIdx.x] = acce + acco;
        __syncthreads();

        const int t = threadIdx.x;
        if (t < EPB) {
            const int i = s + 1 + t;
            if (i >= 0 && i < GRID_G) {
                float a = fv[t], b = fv[t + 1], cc = fv[t + 2], d = fv[t + 3];
                float t3 = fmaf(3.0f, b - cc, d - a);       // -a+3b-3cc+d
                float t2 = fmaf(-2.0f, b, a) + cc - t3;     //  2a-5b+4cc-d
                float4 k;
                k.x = b;
                k.y = 0.5f * (cc - a);
                k.z = 0.5f * t2;
                k.w = 0.5f * t3;
                g_coef[i] = k;
            }
        }
        // publish: last build block releases the flag
        __syncthreads();
        if (threadIdx.x == 0) {
            __threadfence();
            int old = atomicAdd(&g_build_done, 1);
            if (old == BGRID - 1) {
                g_build_done = 0;              // reset for next replay
                st_release(&g_flag, 1);
            }
        }
    } else {
        // ---------------- eval part ----------------
        const float KG     = (float)GRID_G / 20.0f;
        const float CENTER = (float)(GRID_G / 2);

        const int idx = (bid - BGRID) * BLOCK + threadIdx.x;

        // table-independent prologue (hidden under build)
        float4 xv = make_float4(0.f, 0.f, 0.f, 0.f);
        if (idx < N4) xv = __ldcs(&x4[idx]);

        float ti0 = fmaf(xv.x, KG, CENTER);
        float ti1 = fmaf(xv.y, KG, CENTER);
        float ti2 = fmaf(xv.z, KG, CENTER);
        float ti3 = fmaf(xv.w, KG, CENTER);
        int i0 = min(max((int)ti0, 0), GRID_G - 1);
        int i1 = min(max((int)ti1, 0), GRID_G - 1);
        int i2 = min(max((int)ti2, 0), GRID_G - 1);
        int i3 = min(max((int)ti3, 0), GRID_G - 1);
        float f0 = ti0 - (float)i0, f1 = ti1 - (float)i1;
        float f2 = ti2 - (float)i2, f3 = ti3 - (float)i3;

        float xr = 0.0f;
        int   kk = 0;
        bool  has_rem = (idx < (N & 3));
        if (has_rem) { kk = N4 * 4 + idx; xr = __ldcs(&x[kk]); }

        // wait for the table
        if (threadIdx.x == 0) {
            while (ld_acquire(&g_flag) == 0) __nanosleep(64);
        }
        __syncthreads();

        if (idx < N4) {
            float4 r;
            r.x = eval_one(f0, i0);
            r.y = eval_one(f1, i1);
            r.z = eval_one(f2, i2);
            r.w = eval_one(f3, i3);
            __stcs(&out4[idx], r);
        }
        if (has_rem) {
            float tv = fmaf(xr, KG, CENTER);
            int   ii = min(max((int)tv, 0), GRID_G - 1);
            out[kk]  = eval_one(tv - (float)ii, ii);
        }

        // last eval block resets the flag for the next graph replay
        __syncthreads();
        if (threadIdx.x == 0) {
            __threadfence();
            int old = atomicAdd(&g_eval_done, 1);
            if (old == egrid - 1) {
                g_eval_done = 0;
                st_release(&g_flag, 0);
            }
        }
    }
}

extern "C" void kernel_launch(void* const* d_in, const int* in_sizes, int n_in,
                              void* d_out, int out_size)
{
    const int*   n_p  = (const int*)d_in[0];
    const int*   l_p  = (const int*)d_in[1];
    const float* x    = (const float*)d_in[2];
    const float* eig  = (const float*)d_in[3];
    float*       out  = (float*)d_out;

    const int N  = in_sizes[2];
    const int N4 = N >> 2;

    const int egrid = (N4 + BLOCK - 1) / BLOCK;       // 977
    const int grid  = BGRID + egrid;                  // 1010

    fused_kernel<<<grid, BLOCK>>>(n_p, l_p,
                                  (const float4*)x, x, eig,
                                  (float4*)out, out,
                                  N4, N, egrid);
}

// round 16
// speedup vs baseline: 1.3433x; 1.3433x over previous
#include <cuda_runtime.h>
#include <cuda_bf16.h>
#include <math.h>

// out[j] = sum_{m=0}^{199} eigenvectors[l][m][n] * basis(m, x[j])
//   l==0: cos((pi/10)(m+0.5)x)   l>0: sin((pi/10)(m+1)x)
//
// R12: two kernels with PDL (R10 structure — fused R11 regressed, reverted).
// Build tabulates F values over [-pi,pi] (8192 intervals, 33KB). Eval copies
// the table to SHARED memory (random scatter costs bank-conflict degree ~3cyc
// there vs ~1 L1-wavefront per lane for global gathers — the measured R9/R10
// serializer), then 4 LDS taps + Catmull-Rom cubic per point. float4 I/O,
// x-load prologue hoisted above the grid dependency sync.

#define N_MAX    200
#define M_TERMS  200
#define GRID_G   8192               // intervals over [-pi, pi]
#define TABN     (GRID_G + 3)       // taps i-1..i+2 -> 1 front + 2 back guards
#define TABPAD   8196               // multiple of 4 for float4 fill
#define TBLOCK   256
#define EBLOCK   256

__device__ float g_table[TABPAD];

// ---------------- kernel 1: build value table ----------------
// g_table[k] = F(u_k), u_k = (k-1)*h - pi, h = 2*pi/GRID_G.
// Even/odd split: p_{m+2} = 2cos(2u) p_m - p_{m-2}; two 100-step chains.
__global__ __launch_bounds__(TBLOCK)
void build_table_kernel(const int* __restrict__ np,
                        const int* __restrict__ lp,
                        const float* __restrict__ eig)
{
    __shared__ float sc[M_TERMS];
    const int n = np[0];
    const int l = lp[0];
    const float* base = eig + (size_t)l * (N_MAX * N_MAX) + n;
    for (int m = threadIdx.x; m < M_TERMS; m += TBLOCK)
        sc[m] = base[(size_t)m * N_MAX];
    __syncthreads();

    const int g = blockIdx.x * TBLOCK + threadIdx.x;
    if (g < TABN) {
        const float u = (float)((double)(g - 1) * (6.283185307179586 / GRID_G)
                                - 3.141592653589793);
        float si, c;
        sincosf(u, &si, &c);
        const float c22 = fmaf(4.0f * c, c, -2.0f);   // 2cos(2u)

        float pe, pem, po, pom;
        if (l == 0) {
            float h0 = cosf(0.5f * u);
            pe  = h0;                    // p_0  = cos(u/2)
            pem = cosf(1.5f * u);        // p_{-2}= cos(-1.5u)
            po  = pem;                   // p_1  = cos(1.5u)
            pom = h0;                    // p_{-1}= cos(u/2)
        } else {
            pe  = si;                    // p_0  = sin(u)
            pem = -si;                   // p_{-2}= sin(-u)
            po  = 2.0f * si * c;         // p_1  = sin(2u)
            pom = 0.0f;                  // p_{-1}= sin(0)
        }

        float acce = 0.0f, acco = 0.0f;
        #pragma unroll 4
        for (int m = 0; m < M_TERMS; m += 2) {
            acce = fmaf(sc[m],     pe, acce);
            acco = fmaf(sc[m + 1], po, acco);
            float pne = fmaf(c22, pe, -pem);
            float pno = fmaf(c22, po, -pom);
            pem = pe; pe = pne;
            pom = po; po = pno;
        }
        g_table[g] = acce + acco;
    }
#if __CUDA_ARCH__ >= 900
    cudaTriggerProgrammaticLaunchCompletion();
#endif
}

// ---------------- kernel 2: evaluate from shared table ----------------
__device__ __forceinline__ float eval_one(const float* __restrict__ tab,
                                          float f, int i)
{
    float a = tab[i], b = tab[i + 1], c = tab[i + 2], d = tab[i + 3];
    // Catmull-Rom: b + 0.5f[(c-a)f + (2a-5b+4c-d)f^2 + (-a+3b-3c+d)f^3]
    float s1 = c - a;
    float t3 = fmaf(3.0f, b - c, d - a);      // -a+3b-3c+d
    float t2 = fmaf(-2.0f, b, a) + c - t3;    //  2a-5b+4c-d
    float h  = fmaf(f, t3, t2);
    h        = fmaf(f, h, s1);
    return fmaf(0.5f * f, h, b);
}

__global__ __launch_bounds__(EBLOCK)
void eval_kernel(const float4* __restrict__ x4,
                 float4* __restrict__ out4,
                 int N4,
                 const float* __restrict__ x,
                 float* __restrict__ out,
                 int N)
{
    __shared__ float tab[TABPAD];             // 32.8 KB static

    const float KG     = (float)GRID_G / 20.0f;
    const float CENTER = (float)(GRID_G / 2);

    const int idx = blockIdx.x * EBLOCK + threadIdx.x;

    // --- pre-sync prologue: table-independent ---
    float4 xv = make_float4(0.f, 0.f, 0.f, 0.f);
    if (idx < N4) xv = __ldcs(&x4[idx]);

    float ti0 = fmaf(xv.x, KG, CENTER);
    float ti1 = fmaf(xv.y, KG, CENTER);
    float ti2 = fmaf(xv.z, KG, CENTER);
    float ti3 = fmaf(xv.w, KG, CENTER);
    int i0 = min(max((int)ti0, 0), GRID_G - 1);
    int i1 = min(max((int)ti1, 0), GRID_G - 1);
    int i2 = min(max((int)ti2, 0), GRID_G - 1);
    int i3 = min(max((int)ti3, 0), GRID_G - 1);
    float f0 = ti0 - (float)i0, f1 = ti1 - (float)i1;
    float f2 = ti2 - (float)i2, f3 = ti3 - (float)i3;

    float xr = 0.0f;
    int   kk = 0;
    bool  has_rem = (idx < (N & 3));
    if (has_rem) { kk = N4 * 4 + idx; xr = __ldcs(&x[kk]); }

#if __CUDA_ARCH__ >= 900
    cudaGridDependencySynchronize();          // table is ready after this
#endif

    // cooperative fill: 2049 float4s
    {
        const float4* src = (const float4*)g_table;
        float4*       dst = (float4*)tab;
        #pragma unroll
        for (int k = threadIdx.x; k < TABPAD / 4; k += EBLOCK)
            dst[k] = __ldg(&src[k]);
    }
    __syncthreads();

    if (idx < N4) {
        float4 r;
        r.x = eval_one(tab, f0, i0);
        r.y = eval_one(tab, f1, i1);
        r.z = eval_one(tab, f2, i2);
        r.w = eval_one(tab, f3, i3);
        __stcs(&out4[idx], r);
    }
    if (has_rem) {
        float tv = fmaf(xr, KG, CENTER);
        int   ii = min(max((int)tv, 0), GRID_G - 1);
        out[kk]  = eval_one(tab, tv - (float)ii, ii);
    }
}

extern "C" void kernel_launch(void* const* d_in, const int* in_sizes, int n_in,
                              void* d_out, int out_size)
{
    const int*   n_p  = (const int*)d_in[0];
    const int*   l_p  = (const int*)d_in[1];
    const float* x    = (const float*)d_in[2];
    const float* eig  = (const float*)d_in[3];
    float*       out  = (float*)d_out;

    const int N  = in_sizes[2];
    const int N4 = N >> 2;

    const int tgrid = (TABN + TBLOCK - 1) / TBLOCK;   // 33 blocks
    build_table_kernel<<<tgrid, TBLOCK>>>(n_p, l_p, eig);

    const int egrid = (N4 + EBLOCK - 1) / EBLOCK;     // 977 blocks

    cudaLaunchConfig_t cfg = {};
    cfg.gridDim  = dim3((unsigned)egrid, 1, 1);
    cfg.blockDim = dim3(EBLOCK, 1, 1);
    cfg.dynamicSmemBytes = 0;
    cfg.stream = 0;
    cudaLaunchAttribute attr[1];
    attr[0].id = cudaLaunchAttributeProgrammaticStreamSerialization;
    attr[0].val.programmaticStreamSerializationAllowed = 1;
    cfg.attrs = attr;
    cfg.numAttrs = 1;

    cudaError_t e = cudaLaunchKernelEx(&cfg, eval_kernel,
                                       (const float4*)x, (float4*)out, N4,
                                       x, out, N);
    if (e != cudaSuccess) {
        eval_kernel<<<egrid, EBLOCK>>>((const float4*)x, (float4*)out, N4,
                                       x, out, N);
    }
}